// round 16
// baseline (speedup 1.0000x reference)
#include <cuda_runtime.h>
#include <cuda_bf16.h>
#include <math.h>
#include <stdint.h>

// Shapes:
//   x      [32,64,64,512] f32 NHWC
//   base_w [3,3,512,256]  HWIO   (flattened: w[kk*256+n], kk = pos*512+c)
//   base_b [256]
//   cls_w  [1,1,256,9], cls_b [9]
//   reg_w  [1,1,256,36], reg_b [36]
//   out    [32,64,64,45]

#define NPIX    (32 * 64 * 64)
#define KTOT    4608
#define KCH     144                 // k chunks of 32
#define NSTEPS  144
#define AROW_B  80                  // 32 bf16 = 64B + 16B pad (ldmatrix conflict-free)
#define A_HL    (128 * AROW_B)      // 10240 B per A half
#define B_HL    (256 * AROW_B)      // 20480 B per B half (256 n-rows)
#define ABYTES  (2 * A_HL)          // 20480
#define BBYTES  (2 * B_HL)          // 40960
#define STAGE   (ABYTES + BBYTES)   // 61440
#define NSTAGE  3
#define SMEM_TOTAL (NSTAGE * STAGE) // 184320

#define DELTA_REG 5e-3f
#define DELTA_OBJ 5e-4f

__device__ float g_feat[(size_t)NPIX * 256];
__device__ __align__(256) __nv_bfloat16 g_xh16[(size_t)NPIX * 512];
__device__ __align__(256) __nv_bfloat16 g_xl16[(size_t)NPIX * 512];
// B chunks: [kc][n 256][k 32] bf16 -> conv-side fill is a linear copy.
__device__ __align__(256) __nv_bfloat16 g_Bh16[(size_t)KCH * 256 * 32];
__device__ __align__(256) __nv_bfloat16 g_Bl16[(size_t)KCH * 256 * 32];
__device__ __align__(256) float g_zero[16];   // 64B, stays zero
__device__ int g_count;
__device__ int g_list[NPIX];

// ---------------- helpers ----------------
__device__ __forceinline__ uint32_t smem_u32(const void* p) {
    uint32_t a;
    asm("{ .reg .u64 t; cvta.to.shared.u64 t, %1; cvt.u32.u64 %0, t; }"
        : "=r"(a) : "l"(p));
    return a;
}
__device__ __forceinline__ void cp16(uint32_t d, const void* s) {
    asm volatile("cp.async.ca.shared.global [%0], [%1], 16;"
                 :: "r"(d), "l"(s) : "memory");
}
__device__ __forceinline__ void ldm_x4(uint32_t* r, uint32_t addr) {
    asm volatile("ldmatrix.sync.aligned.m8n8.x4.shared.b16 {%0,%1,%2,%3}, [%4];"
                 : "=r"(r[0]), "=r"(r[1]), "=r"(r[2]), "=r"(r[3]) : "r"(addr));
}
__device__ __forceinline__ void mma_bf16(float* c, const uint32_t* a,
                                         uint32_t b0, uint32_t b1) {
    asm volatile(
        "mma.sync.aligned.m16n8k16.row.col.f32.bf16.bf16.f32 "
        "{%0,%1,%2,%3}, {%4,%5,%6,%7}, {%8,%9}, {%0,%1,%2,%3};"
        : "+f"(c[0]), "+f"(c[1]), "+f"(c[2]), "+f"(c[3])
        : "r"(a[0]), "r"(a[1]), "r"(a[2]), "r"(a[3]), "r"(b0), "r"(b1));
}
__device__ __forceinline__ uint32_t pack2(float x, float y) {
    const __nv_bfloat162 h2 = __floats2bfloat162_rn(x, y);
    return *(const uint32_t*)&h2;
}

// ---------------------------------------------------------------------------
__global__ void reset_kernel() { g_count = 0; }

// ---------------------------------------------------------------------------
// Prep: bf16 hi/lo split of x (4 floats per thread).
// ---------------------------------------------------------------------------
__global__ void prep_x_kernel(const float* __restrict__ x)
{
    const size_t i = ((size_t)blockIdx.x * 256 + threadIdx.x) * 4;
    const float4 v = *(const float4*)(x + i);
    float hx = __bfloat162float(__float2bfloat16_rn(v.x));
    float hy = __bfloat162float(__float2bfloat16_rn(v.y));
    float hz = __bfloat162float(__float2bfloat16_rn(v.z));
    float hw = __bfloat162float(__float2bfloat16_rn(v.w));
    uint2 ho, lo;
    ho.x = pack2(hx, hy);
    ho.y = pack2(hz, hw);
    lo.x = pack2(v.x - hx, v.y - hy);
    lo.y = pack2(v.z - hz, v.w - hw);
    *(uint2*)((char*)g_xh16 + i * 2) = ho;
    *(uint2*)((char*)g_xl16 + i * 2) = lo;
}

// ---------------------------------------------------------------------------
// Prep: base_w -> bf16 hi/lo chunks [kc][n][k32].
// ---------------------------------------------------------------------------
__global__ void prep_b_kernel(const float* __restrict__ w)
{
    const int idx = blockIdx.x * 256 + threadIdx.x;    // 0..294911
    const int kc  = idx >> 11;
    const int rem = idx & 2047;
    const int n   = rem >> 3;
    const int q   = rem & 7;
    const int k0  = q * 4;

    float v[4], h[4];
#pragma unroll
    for (int j = 0; j < 4; j++) {
        v[j] = w[(size_t)(kc * 32 + k0 + j) * 256 + n];
        h[j] = __bfloat162float(__float2bfloat16_rn(v[j]));
    }
    uint2 ho, lo;
    ho.x = pack2(h[0], h[1]);
    ho.y = pack2(h[2], h[3]);
    lo.x = pack2(v[0] - h[0], v[1] - h[1]);
    lo.y = pack2(v[2] - h[2], v[3] - h[3]);
    const size_t off = ((size_t)kc * 256 + n) * 32 + k0;
    *(uint2*)((char*)g_Bh16 + off * 2) = ho;
    *(uint2*)((char*)g_Bl16 + off * 2) = lo;
}

// ---------------------------------------------------------------------------
// Stage 1: 3x3 conv + bias + ReLU via mma.sync m16n8k16 BF16x3 implicit GEMM.
// CTA: 512 threads (16 warps, 4x4 warp grid), tile M=128 x N=256,
// K=4608 in 144 chunks of 32. ldmatrix loads, 3-stage cp.async (wait_group 1).
// ---------------------------------------------------------------------------
__global__ void __launch_bounds__(512, 1)
conv_mma_kernel(const float* __restrict__ bbase)
{
    extern __shared__ char smem[];
    const uint32_t sb = smem_u32(smem);
    const int tid  = threadIdx.x;
    const int wid  = tid >> 5;
    const int lane = tid & 31;
    const int g    = lane >> 2;
    const int t    = lane & 3;
    const int mblk = blockIdx.x;          // 0..1023
    const int wm   = (wid >> 2) * 32;     // warp row 0/32/64/96
    const int wn   = (wid & 3) * 64;      // warp col 0/64/128/192

    // ---- fill-side mappings ----
    // A: 512 slots = 128 rows x 2 halves x 2 parts(32B)
    const int arow  = tid >> 2;
    const int ahalf = (tid >> 1) & 1;
    const int apart = tid & 1;
    const int p  = mblk * 128 + arow;
    const int pb = p >> 12;
    const int ph = (p >> 6) & 63;
    const int pw = p & 63;
    // B: 512 slots = 256 n-rows x 2 halves (64B each)
    const int bn    = tid >> 1;
    const int bhalf = tid & 1;

    // ldmatrix lane offset: rows via lane%16, k(+8) via lane/16
    const uint32_t lmoff = (uint32_t)(lane & 15) * AROW_B +
                           (uint32_t)(lane >> 4) * 16;

    float bias[16];
#pragma unroll
    for (int ni = 0; ni < 8; ni++) {
        const int ch = wn + ni * 8 + 2 * t;
        bias[2 * ni + 0] = __ldg(&bbase[ch + 0]);
        bias[2 * ni + 1] = __ldg(&bbase[ch + 1]);
    }

    float C[2][8][4];
#pragma unroll
    for (int mi = 0; mi < 2; mi++)
#pragma unroll
        for (int ni = 0; ni < 8; ni++)
#pragma unroll
            for (int r = 0; r < 4; r++) C[mi][ni][r] = 0.0f;

    auto fill = [&](int kc, int stg) {
        const uint32_t base = sb + (uint32_t)stg * STAGE;
        // A slice
        const int pos = kc >> 4;
        const int ky  = pos / 3;
        const int kx  = pos - ky * 3;
        const int hin = ph + ky - 1;
        const int win = pw + kx - 1;
        const bool valid = ((unsigned)hin < 64u) && ((unsigned)win < 64u);
        const int c0 = (kc & 15) * 32 + apart * 16;
        const __nv_bfloat16* xsrc = ahalf ? g_xl16 : g_xh16;
        const char* asrc = valid
            ? (const char*)(xsrc + ((size_t)((pb * 64 + hin) * 64 + win)) * 512 + c0)
            : (const char*)g_zero;
        const uint32_t adst = base + (uint32_t)ahalf * A_HL +
                              (uint32_t)arow * AROW_B + (uint32_t)apart * 32;
        cp16(adst,      asrc);
        cp16(adst + 16, asrc + 16);

        // B slice (linear copy of pre-chunked weights)
        const __nv_bfloat16* bsrc16 = bhalf ? g_Bl16 : g_Bh16;
        const char* bsrc = (const char*)(bsrc16 + ((size_t)kc * 256 + bn) * 32);
        const uint32_t bdst = base + ABYTES + (uint32_t)bhalf * B_HL +
                              (uint32_t)bn * AROW_B;
#pragma unroll
        for (int i = 0; i < 4; i++) cp16(bdst + i * 16, bsrc + i * 16);

        asm volatile("cp.async.commit_group;" ::: "memory");
    };

    fill(0, 0);
    fill(1, 1);

#pragma unroll 1
    for (int step = 0; step < NSTEPS; step++) {
        if (step + 1 < NSTEPS)
            asm volatile("cp.async.wait_group 1;" ::: "memory");
        else
            asm volatile("cp.async.wait_group 0;" ::: "memory");
        __syncthreads();
        if (step + 2 < NSTEPS) fill(step + 2, (step + 2) % NSTAGE);

        const uint32_t base  = sb + (uint32_t)(step % NSTAGE) * STAGE;
        const uint32_t abase = base + (uint32_t)wm * AROW_B + lmoff;
        const uint32_t bbs   = base + ABYTES + (uint32_t)wn * AROW_B + lmoff;

#pragma unroll
        for (int s = 0; s < 2; s++) {            // two k16 groups per chunk
            const uint32_t ks = (uint32_t)s * 32;

            uint32_t ah[2][4];
            ldm_x4(ah[0], abase + ks);
            ldm_x4(ah[1], abase + 16 * AROW_B + ks);

            uint32_t bh[4][4];                   // [nq]: r0=b0(ni even) r1=b0(odd)
#pragma unroll                                   //       r2=b1(even)  r3=b1(odd)
            for (int nq = 0; nq < 4; nq++)
                ldm_x4(bh[nq], bbs + (uint32_t)nq * 16 * AROW_B + ks);

            // pass hh
#pragma unroll
            for (int mi = 0; mi < 2; mi++)
#pragma unroll
                for (int nq = 0; nq < 4; nq++) {
                    mma_bf16(C[mi][2 * nq + 0], ah[mi], bh[nq][0], bh[nq][2]);
                    mma_bf16(C[mi][2 * nq + 1], ah[mi], bh[nq][1], bh[nq][3]);
                }

            // pass lh (al x bh)
            uint32_t al[2][4];
            ldm_x4(al[0], abase + A_HL + ks);
            ldm_x4(al[1], abase + A_HL + 16 * AROW_B + ks);
#pragma unroll
            for (int mi = 0; mi < 2; mi++)
#pragma unroll
                for (int nq = 0; nq < 4; nq++) {
                    mma_bf16(C[mi][2 * nq + 0], al[mi], bh[nq][0], bh[nq][2]);
                    mma_bf16(C[mi][2 * nq + 1], al[mi], bh[nq][1], bh[nq][3]);
                }

            // pass hl (ah x bl)
            uint32_t bl[4][4];
#pragma unroll
            for (int nq = 0; nq < 4; nq++)
                ldm_x4(bl[nq], bbs + B_HL + (uint32_t)nq * 16 * AROW_B + ks);
#pragma unroll
            for (int mi = 0; mi < 2; mi++)
#pragma unroll
                for (int nq = 0; nq < 4; nq++) {
                    mma_bf16(C[mi][2 * nq + 0], ah[mi], bl[nq][0], bl[nq][2]);
                    mma_bf16(C[mi][2 * nq + 1], ah[mi], bl[nq][1], bl[nq][3]);
                }
        }
    }

    // Epilogue: bias + ReLU -> g_feat
#pragma unroll
    for (int mi = 0; mi < 2; mi++) {
        const int row0 = mblk * 128 + wm + mi * 16 + g;
#pragma unroll
        for (int ni = 0; ni < 8; ni++) {
            const int ch = wn + ni * 8 + 2 * t;
            float2 v0, v1;
            v0.x = fmaxf(C[mi][ni][0] + bias[2 * ni + 0], 0.f);
            v0.y = fmaxf(C[mi][ni][1] + bias[2 * ni + 1], 0.f);
            v1.x = fmaxf(C[mi][ni][2] + bias[2 * ni + 0], 0.f);
            v1.y = fmaxf(C[mi][ni][3] + bias[2 * ni + 1], 0.f);
            *(float2*)(g_feat + (size_t)row0 * 256 + ch)       = v0;
            *(float2*)(g_feat + (size_t)(row0 + 8) * 256 + ch) = v1;
        }
    }
}

// ---------------------------------------------------------------------------
// Stage 2: fused 1x1 heads + sigmoid + anchor filter + concat store.
// Flags pixels with any anchor within delta of a decision threshold.
// ---------------------------------------------------------------------------
__global__ void __launch_bounds__(256)
rpn_head_kernel(const float* __restrict__ cls_w,
                const float* __restrict__ cls_b,
                const float* __restrict__ reg_w,
                const float* __restrict__ reg_b,
                float* __restrict__ out)
{
    __shared__ float wsm[256 * 45];
    for (int idx = threadIdx.x; idx < 256 * 45; idx += 256) {
        const int c = idx / 45;
        const int j = idx - c * 45;
        wsm[idx] = (j < 36) ? reg_w[c * 36 + j] : cls_w[c * 9 + (j - 36)];
    }
    __syncthreads();

    const int p = blockIdx.x * 256 + threadIdx.x;
    const float* f = g_feat + (size_t)p * 256;

    float acc[45];
#pragma unroll
    for (int j = 0; j < 45; j++) acc[j] = 0.0f;

#pragma unroll 1
    for (int c4 = 0; c4 < 64; c4++) {
        const float4 fv = *(const float4*)(f + c4 * 4);
        const float* w0 = &wsm[(c4 * 4 + 0) * 45];
        const float* w1 = &wsm[(c4 * 4 + 1) * 45];
        const float* w2 = &wsm[(c4 * 4 + 2) * 45];
        const float* w3 = &wsm[(c4 * 4 + 3) * 45];
#pragma unroll
        for (int j = 0; j < 45; j++) {
            float tt = acc[j];
            tt = fmaf(fv.x, w0[j], tt);
            tt = fmaf(fv.y, w1[j], tt);
            tt = fmaf(fv.z, w2[j], tt);
            tt = fmaf(fv.w, w3[j], tt);
            acc[j] = tt;
        }
    }

#pragma unroll
    for (int j = 0; j < 36; j++) acc[j] += reg_b[j];
#pragma unroll
    for (int a = 0; a < 9; a++) {
        const float z = acc[36 + a] + cls_b[a];
        acc[36 + a] = 1.0f / (1.0f + expf(-z));
    }

    bool flag = false;
    float* o = out + (size_t)p * 45;
#pragma unroll
    for (int a = 0; a < 9; a++) {
        const float obj = acc[36 + a];
        const float w2v = acc[4 * a + 2];
        const float h2v = acc[4 * a + 3];
        flag |= (fabsf(w2v - 10.0f) < DELTA_REG) ||
                (fabsf(h2v - 10.0f) < DELTA_REG) ||
                (fabsf(obj - 0.7f)  < DELTA_OBJ);
        const bool keep = (obj > 0.7f) && (w2v > 10.0f) && (h2v > 10.0f);
        const float m = keep ? 1.0f : 0.0f;
        o[4 * a + 0] = acc[4 * a + 0] * m;
        o[4 * a + 1] = acc[4 * a + 1] * m;
        o[4 * a + 2] = w2v * m;
        o[4 * a + 3] = h2v * m;
        o[36 + a]    = obj;
    }
    if (flag) {
        const int i = atomicAdd(&g_count, 1);
        g_list[i] = p;
    }
}

// ---------------------------------------------------------------------------
// Stage 3: exact fp32 repair of flagged (threshold-adjacent) pixels.
// ---------------------------------------------------------------------------
__global__ void __launch_bounds__(256)
repair_kernel(const float* __restrict__ x,  const float* __restrict__ w,
              const float* __restrict__ bbase,
              const float* __restrict__ cls_w, const float* __restrict__ cls_b,
              const float* __restrict__ reg_w, const float* __restrict__ reg_b,
              float* __restrict__ out)
{
    __shared__ float xs[KTOT];
    __shared__ float feats[256];
    __shared__ float hsm[45];
    const int tid = threadIdx.x;
    const int cnt = g_count;

    for (int it = blockIdx.x; it < cnt; it += gridDim.x) {
        const int p  = g_list[it];
        const int pb = p >> 12;
        const int ph = (p >> 6) & 63;
        const int pw = p & 63;

#pragma unroll 1
        for (int pos = 0; pos < 9; pos++) {
            const int ky = pos / 3;
            const int kx = pos - ky * 3;
            const int hin = ph + ky - 1;
            const int win = pw + kx - 1;
            const bool valid = ((unsigned)hin < 64u) && ((unsigned)win < 64u);
            const float* src = x + ((size_t)((pb * 64 + hin) * 64 + win)) * 512;
#pragma unroll
            for (int c = tid; c < 512; c += 256)
                xs[pos * 512 + c] = valid ? src[c] : 0.0f;
        }
        __syncthreads();

        float a0 = 0.f, a1 = 0.f, a2 = 0.f, a3 = 0.f;
#pragma unroll 4
        for (int kk = 0; kk < KTOT; kk += 4) {
            a0 = fmaf(xs[kk + 0], w[(size_t)(kk + 0) * 256 + tid], a0);
            a1 = fmaf(xs[kk + 1], w[(size_t)(kk + 1) * 256 + tid], a1);
            a2 = fmaf(xs[kk + 2], w[(size_t)(kk + 2) * 256 + tid], a2);
            a3 = fmaf(xs[kk + 3], w[(size_t)(kk + 3) * 256 + tid], a3);
        }
        feats[tid] = fmaxf((a0 + a1) + (a2 + a3) + bbase[tid], 0.0f);
        __syncthreads();

        if (tid < 45) {
            float a = 0.f;
            if (tid < 36) {
#pragma unroll 4
                for (int c = 0; c < 256; c++)
                    a = fmaf(feats[c], reg_w[c * 36 + tid], a);
                a += reg_b[tid];
            } else {
                const int j = tid - 36;
#pragma unroll 4
                for (int c = 0; c < 256; c++)
                    a = fmaf(feats[c], cls_w[c * 9 + j], a);
                a = 1.0f / (1.0f + expf(-(a + cls_b[j])));
            }
            hsm[tid] = a;
        }
        __syncthreads();

        if (tid < 9) {
            const int a4 = tid * 4;
            const float obj = hsm[36 + tid];
            const bool keep = (obj > 0.7f) && (hsm[a4 + 2] > 10.0f) &&
                              (hsm[a4 + 3] > 10.0f);
            const float m = keep ? 1.0f : 0.0f;
            float* o = out + (size_t)p * 45;
            o[a4 + 0] = hsm[a4 + 0] * m;
            o[a4 + 1] = hsm[a4 + 1] * m;
            o[a4 + 2] = hsm[a4 + 2] * m;
            o[a4 + 3] = hsm[a4 + 3] * m;
            o[36 + tid] = obj;
        }
        __syncthreads();
    }
}

extern "C" void kernel_launch(void* const* d_in, const int* in_sizes, int n_in,
                              void* d_out, int out_size)
{
    const float* x      = (const float*)d_in[0];
    const float* base_w = (const float*)d_in[1];
    const float* base_b = (const float*)d_in[2];
    const float* cls_w  = (const float*)d_in[3];
    const float* cls_b  = (const float*)d_in[4];
    const float* reg_w  = (const float*)d_in[5];
    const float* reg_b  = (const float*)d_in[6];
    float* out = (float*)d_out;

    cudaFuncSetAttribute(conv_mma_kernel,
                         cudaFuncAttributeMaxDynamicSharedMemorySize, SMEM_TOTAL);

    reset_kernel<<<1, 1>>>();
    prep_x_kernel<<<(NPIX * 512 / 4) / 256, 256>>>(x);
    prep_b_kernel<<<(KCH * 256 * 8) / 256, 256>>>(base_w);

    conv_mma_kernel<<<1024, 512, SMEM_TOTAL>>>(base_b);
    rpn_head_kernel<<<512, 256>>>(cls_w, cls_b, reg_w, reg_b, out);
    repair_kernel<<<256, 256>>>(x, base_w, base_b, cls_w, cls_b,
                                reg_w, reg_b, out);
}